// round 4
// baseline (speedup 1.0000x reference)
#include <cuda_runtime.h>

#define Bb    8
#define Hh    512
#define Ll    8192
#define NFFT  16384
#define HALF  8192
#define NPAIR 256   /* H/2 */
#define TFFT  512

// ---------------- scratch (device globals; no allocation allowed) ----------------
__device__ float4 g_AB[(size_t)NPAIR * (HALF + 1)];        // ~33.5 MB: per-pair combined spectra A,B
__device__ float  g_ymid[(size_t)Bb * Hh * Ll];            // ~134 MB: conv+skip result (B,H,L)

// ---------------- helpers ----------------
__device__ __forceinline__ float2 cmulf(float2 a, float2 b) {
    return make_float2(a.x * b.x - a.y * b.y, a.x * b.y + a.y * b.x);
}

// base-4 digit reversal of a 14-bit index (N=16384 = 4^7):
// bit-reverse 14 bits, then swap adjacent bit pairs.
__device__ __forceinline__ int rev4_14(int k) {
    unsigned r = __brev((unsigned)k) >> 18;
    return (int)(((r & 0x2AAAu) >> 1) | ((r & 0x1555u) << 1));
}

// In-place radix-4 DIF forward FFT (e^{-2pi i}), natural input -> digit-reversed output.
__device__ void dif_fft(float2* s, int tid) {
#pragma unroll 1
    for (int m = NFFT; m >= 4; m >>= 2) {
        int q = m >> 2;
#pragma unroll 1
        for (int i = tid; i < NFFT / 4; i += TFFT) {
            int j = i & (q - 1);
            int base = ((i - j) << 2) + j;     // (i/q)*m + j
            float2 a0 = s[base], a1 = s[base + q], a2 = s[base + 2 * q], a3 = s[base + 3 * q];
            float t0x = a0.x + a2.x, t0y = a0.y + a2.y;
            float t1x = a0.x - a2.x, t1y = a0.y - a2.y;
            float t2x = a1.x + a3.x, t2y = a1.y + a3.y;
            float t3x = a1.x - a3.x, t3y = a1.y - a3.y;
            float2 b0 = make_float2(t0x + t2x, t0y + t2y);
            float2 b1 = make_float2(t1x + t3y, t1y - t3x);   // t1 - i*t3
            float2 b2 = make_float2(t0x - t2x, t0y - t2y);
            float2 b3 = make_float2(t1x - t3y, t1y + t3x);   // t1 + i*t3
            float ang = (-6.283185307179586f) * ((float)j / (float)m);
            float sn, cs;
            __sincosf(ang, &sn, &cs);
            float2 w1 = make_float2(cs, sn);
            float2 w2 = cmulf(w1, w1);
            float2 w3 = cmulf(w2, w1);
            s[base]         = b0;
            s[base + q]     = cmulf(b1, w1);
            s[base + 2 * q] = cmulf(b2, w2);
            s[base + 3 * q] = cmulf(b3, w3);
        }
        __syncthreads();
    }
}

// In-place radix-4 DIT forward FFT (e^{-2pi i}), digit-reversed input -> natural output.
// (Exact transpose network of dif_fft: twiddle-before-DFT4, ascending m.)
__device__ void dit_fft(float2* s, int tid) {
#pragma unroll 1
    for (int m = 4; m <= NFFT; m <<= 2) {
        int q = m >> 2;
#pragma unroll 1
        for (int i = tid; i < NFFT / 4; i += TFFT) {
            int j = i & (q - 1);
            int base = ((i - j) << 2) + j;
            float2 c0 = s[base], c1 = s[base + q], c2 = s[base + 2 * q], c3 = s[base + 3 * q];
            float ang = (-6.283185307179586f) * ((float)j / (float)m);
            float sn, cs;
            __sincosf(ang, &sn, &cs);
            float2 w1 = make_float2(cs, sn);
            float2 w2 = cmulf(w1, w1);
            float2 w3 = cmulf(w2, w1);
            c1 = cmulf(c1, w1);
            c2 = cmulf(c2, w2);
            c3 = cmulf(c3, w3);
            float t0x = c0.x + c2.x, t0y = c0.y + c2.y;
            float t1x = c0.x - c2.x, t1y = c0.y - c2.y;
            float t2x = c1.x + c3.x, t2y = c1.y + c3.y;
            float t3x = c1.x - c3.x, t3y = c1.y - c3.y;
            s[base]         = make_float2(t0x + t2x, t0y + t2y);
            s[base + q]     = make_float2(t1x + t3y, t1y - t3x);  // t1 - i*t3
            s[base + 2 * q] = make_float2(t0x - t2x, t0y - t2y);
            s[base + 3 * q] = make_float2(t1x - t3y, t1y + t3x);  // t1 + i*t3
        }
        __syncthreads();
    }
}

// ---------------- kernel 1: precompute combined kernel spectra A,B per channel pair ----------------
// z = K[2p] + i K[2p+1] (zero-padded). After DIF, Z[k] at slot rev4(k).
// A[k] = ((1-i)Z[k] + (1+i)conj(Z[N-k])) / (4N)   (= (K1f+K2f)/(2N))
// B[k] = ((1+i)Z[k] + (1-i)conj(Z[N-k])) / (4N)   (= (K1f-K2f)/(2N))
__global__ void __launch_bounds__(TFFT, 1) kf_kernel(const float* __restrict__ K) {
    extern __shared__ float2 s[];
    int tid  = threadIdx.x;
    int pair = blockIdx.x;
    const float* k1 = K + (size_t)(2 * pair) * Ll;
    const float* k2 = K + (size_t)(2 * pair + 1) * Ll;
    for (int n = tid; n < Ll; n += TFFT) s[n] = make_float2(k1[n], k2[n]);
    for (int n = Ll + tid; n < NFFT; n += TFFT) s[n] = make_float2(0.f, 0.f);
    __syncthreads();
    dif_fft(s, tid);
    const float inv = 1.0f / (4.0f * (float)NFFT);
    float4* AB = g_AB + (size_t)pair * (HALF + 1);
    for (int k = tid; k <= HALF; k += TFFT) {
        int pk  = rev4_14(k);
        int kn  = (NFFT - k) & (NFFT - 1);
        int pk2 = rev4_14(kn);
        float2 Z  = s[pk];
        float2 Zp = s[pk2];
        float ax = (Z.x + Z.y + Zp.x + Zp.y) * inv;
        float ay = (Z.y - Z.x + Zp.x - Zp.y) * inv;
        float bx = (Z.x - Z.y + Zp.x - Zp.y) * inv;
        float by = (Z.x + Z.y - Zp.x - Zp.y) * inv;
        AB[k] = make_float4(ax, ay, bx, by);
    }
}

// ---------------- kernel 2: FFT conv + skip per (batch, channel pair) ----------------
// V[k] = Z[k]*A[k] + conj(Z[N-k])*B[k]; store conj(V) scrambled; DIT gives conj(N*ifft(V)):
// y1 = Re, y2 = -Im. Then add D*u skip and write y_mid (B,H,L).
__global__ void __launch_bounds__(TFFT, 1) conv_kernel(const float* __restrict__ u,
                                                       const float* __restrict__ D) {
    extern __shared__ float2 s[];
    int tid  = threadIdx.x;
    int pair = blockIdx.x & (NPAIR - 1);
    int b    = blockIdx.x >> 8;
    int h1   = 2 * pair, h2 = h1 + 1;
    const float* u1 = u + ((size_t)b * Hh + h1) * Ll;
    const float* u2 = u + ((size_t)b * Hh + h2) * Ll;
    for (int n = tid; n < Ll; n += TFFT) s[n] = make_float2(u1[n], u2[n]);
    for (int n = Ll + tid; n < NFFT; n += TFFT) s[n] = make_float2(0.f, 0.f);
    __syncthreads();
    dif_fft(s, tid);

    const float4* AB = g_AB + (size_t)pair * (HALF + 1);
    for (int k = tid; k <= HALF; k += TFFT) {
        int pk  = rev4_14(k);
        int kn  = (NFFT - k) & (NFFT - 1);
        int pk2 = rev4_14(kn);
        float2 Z  = s[pk];
        float2 Zp = s[pk2];
        float4 ab = AB[k];
        // V[k] = Z*A + conj(Zp)*B
        float vx = Z.x * ab.x - Z.y * ab.y + Zp.x * ab.z + Zp.y * ab.w;
        float vy = Z.x * ab.y + Z.y * ab.x - Zp.y * ab.z + Zp.x * ab.w;
        s[pk] = make_float2(vx, -vy);  // store conj(V[k])
        if (k != 0 && k != HALF) {
            // V[N-k] = Zp*conj(A) + conj(Z)*conj(B)
            float wx =  Zp.x * ab.x + Zp.y * ab.y + Z.x * ab.z - Z.y * ab.w;
            float wy = -Zp.x * ab.y + Zp.y * ab.x - Z.x * ab.w - Z.y * ab.z;
            s[pk2] = make_float2(wx, -wy);
        }
    }
    __syncthreads();
    dit_fft(s, tid);

    float d1 = D[h1], d2 = D[h2];
    float* y1 = g_ymid + ((size_t)b * Hh + h1) * Ll;
    float* y2 = g_ymid + ((size_t)b * Hh + h2) * Ll;
    for (int n = tid; n < Ll; n += TFFT) {
        float2 w = s[n];
        y1[n] =  w.x + d1 * u1[n];
        y2[n] = -w.y + d2 * u2[n];
    }
}

// ---------------- kernel 3: channel mix GEMM + tanh ----------------
// out[b,p,l] = tanh( sum_h W[p,h] * ymid[b,h,l] ).  A = W (row-major MxK), B = ymid[b] (row-major KxN).
__global__ void __launch_bounds__(256, 2) mix_kernel(const float* __restrict__ W,
                                                     float* __restrict__ out) {
    __shared__ float As[8][128];
    __shared__ float Bs[8][128];
    int b = blockIdx.z;
    const float* Yb = g_ymid + (size_t)b * Hh * Ll;
    float* Ob = out + (size_t)b * Hh * Ll;
    int tileN = blockIdx.x * 128;
    int tileM = blockIdx.y * 128;
    int t  = threadIdx.x;
    int ty = t >> 4, tx = t & 15;
    int aRow = t >> 1, aCol = (t & 1) << 2;
    int bRow = t >> 5, bCol = (t & 31) << 2;

    float acc[8][8];
#pragma unroll
    for (int i = 0; i < 8; i++)
#pragma unroll
        for (int j = 0; j < 8; j++) acc[i][j] = 0.f;

    for (int k0 = 0; k0 < Hh; k0 += 8) {
        float4 av = *(const float4*)(W + (size_t)(tileM + aRow) * Hh + k0 + aCol);
        As[aCol + 0][aRow] = av.x;
        As[aCol + 1][aRow] = av.y;
        As[aCol + 2][aRow] = av.z;
        As[aCol + 3][aRow] = av.w;
        float4 bv = *(const float4*)(Yb + (size_t)(k0 + bRow) * Ll + tileN + bCol);
        *(float4*)(&Bs[bRow][bCol]) = bv;
        __syncthreads();
#pragma unroll
        for (int kk = 0; kk < 8; kk++) {
            float ar[8], br[8];
#pragma unroll
            for (int i = 0; i < 8; i++) ar[i] = As[kk][ty * 8 + i];
#pragma unroll
            for (int j = 0; j < 8; j++) br[j] = Bs[kk][tx * 8 + j];
#pragma unroll
            for (int i = 0; i < 8; i++)
#pragma unroll
                for (int j = 0; j < 8; j++) acc[i][j] = fmaf(ar[i], br[j], acc[i][j]);
        }
        __syncthreads();
    }

#pragma unroll
    for (int i = 0; i < 8; i++) {
        int p = tileM + ty * 8 + i;
        float* orow = Ob + (size_t)p * Ll + tileN + tx * 8;
        float4 o0 = make_float4(tanhf(acc[i][0]), tanhf(acc[i][1]), tanhf(acc[i][2]), tanhf(acc[i][3]));
        float4 o1 = make_float4(tanhf(acc[i][4]), tanhf(acc[i][5]), tanhf(acc[i][6]), tanhf(acc[i][7]));
        *(float4*)orow       = o0;
        *(float4*)(orow + 4) = o1;
    }
}

// ---------------- launch ----------------
extern "C" void kernel_launch(void* const* d_in, const int* in_sizes, int n_in,
                              void* d_out, int out_size) {
    const float* u = (const float*)d_in[0];
    const float* K = (const float*)d_in[1];
    const float* D = (const float*)d_in[2];
    const float* W = (const float*)d_in[3];
    float* out = (float*)d_out;

    const int smem = NFFT * (int)sizeof(float2);  // 128 KB
    cudaFuncSetAttribute(kf_kernel,   cudaFuncAttributeMaxDynamicSharedMemorySize, smem);
    cudaFuncSetAttribute(conv_kernel, cudaFuncAttributeMaxDynamicSharedMemorySize, smem);

    kf_kernel<<<NPAIR, TFFT, smem>>>(K);
    conv_kernel<<<Bb * NPAIR, TFFT, smem>>>(u, D);
    dim3 g(Ll / 128, Hh / 128, Bb);
    mix_kernel<<<g, 256>>>(W, out);
}

// round 7
// speedup vs baseline: 1.4844x; 1.4844x over previous
#include <cuda_runtime.h>
#include <cstdint>

#define Bb    8
#define Hh    512
#define Ll    8192
#define NFFT  16384
#define HALF  8192
#define NPAIR 256   /* H/2 */
#define TFFT  512

// ---------------- scratch (device globals; no allocation allowed) ----------------
__device__ float4 g_AB[(size_t)NPAIR * (HALF + 1)];        // ~33.5 MB: per-pair combined spectra A,B
__device__ float  g_ymid[(size_t)Bb * Hh * Ll];            // ~134 MB: conv+skip result (B,H,L), tf32-rounded
__device__ float  g_Wr[(size_t)Hh * Hh];                   // 1 MB: W pre-rounded to tf32 (rna)

// ---------------- helpers ----------------
__device__ __forceinline__ float2 cmulf(float2 a, float2 b) {
    return make_float2(a.x * b.x - a.y * b.y, a.x * b.y + a.y * b.x);
}

__device__ __forceinline__ int rev4_14(int k) {
    unsigned r = __brev((unsigned)k) >> 18;
    return (int)(((r & 0x2AAAu) >> 1) | ((r & 0x1555u) << 1));
}

__device__ __forceinline__ float tf32r(float v) {
    uint32_t r;
    asm("cvt.rna.tf32.f32 %0, %1;" : "=r"(r) : "f"(v));
    return __uint_as_float(r);
}

// In-place radix-4 DIF forward FFT, natural input -> digit-reversed output.
__device__ void dif_fft(float2* s, int tid) {
#pragma unroll 1
    for (int m = NFFT; m >= 4; m >>= 2) {
        int q = m >> 2;
#pragma unroll 1
        for (int i = tid; i < NFFT / 4; i += TFFT) {
            int j = i & (q - 1);
            int base = ((i - j) << 2) + j;
            float2 a0 = s[base], a1 = s[base + q], a2 = s[base + 2 * q], a3 = s[base + 3 * q];
            float t0x = a0.x + a2.x, t0y = a0.y + a2.y;
            float t1x = a0.x - a2.x, t1y = a0.y - a2.y;
            float t2x = a1.x + a3.x, t2y = a1.y + a3.y;
            float t3x = a1.x - a3.x, t3y = a1.y - a3.y;
            float2 b0 = make_float2(t0x + t2x, t0y + t2y);
            float2 b1 = make_float2(t1x + t3y, t1y - t3x);
            float2 b2 = make_float2(t0x - t2x, t0y - t2y);
            float2 b3 = make_float2(t1x - t3y, t1y + t3x);
            float ang = (-6.283185307179586f) * ((float)j / (float)m);
            float sn, cs;
            __sincosf(ang, &sn, &cs);
            float2 w1 = make_float2(cs, sn);
            float2 w2 = cmulf(w1, w1);
            float2 w3 = cmulf(w2, w1);
            s[base]         = b0;
            s[base + q]     = cmulf(b1, w1);
            s[base + 2 * q] = cmulf(b2, w2);
            s[base + 3 * q] = cmulf(b3, w3);
        }
        __syncthreads();
    }
}

// In-place radix-4 DIT forward FFT, digit-reversed input -> natural output.
__device__ void dit_fft(float2* s, int tid) {
#pragma unroll 1
    for (int m = 4; m <= NFFT; m <<= 2) {
        int q = m >> 2;
#pragma unroll 1
        for (int i = tid; i < NFFT / 4; i += TFFT) {
            int j = i & (q - 1);
            int base = ((i - j) << 2) + j;
            float2 c0 = s[base], c1 = s[base + q], c2 = s[base + 2 * q], c3 = s[base + 3 * q];
            float ang = (-6.283185307179586f) * ((float)j / (float)m);
            float sn, cs;
            __sincosf(ang, &sn, &cs);
            float2 w1 = make_float2(cs, sn);
            float2 w2 = cmulf(w1, w1);
            float2 w3 = cmulf(w2, w1);
            c1 = cmulf(c1, w1);
            c2 = cmulf(c2, w2);
            c3 = cmulf(c3, w3);
            float t0x = c0.x + c2.x, t0y = c0.y + c2.y;
            float t1x = c0.x - c2.x, t1y = c0.y - c2.y;
            float t2x = c1.x + c3.x, t2y = c1.y + c3.y;
            float t3x = c1.x - c3.x, t3y = c1.y - c3.y;
            s[base]         = make_float2(t0x + t2x, t0y + t2y);
            s[base + q]     = make_float2(t1x + t3y, t1y - t3x);
            s[base + 2 * q] = make_float2(t0x - t2x, t0y - t2y);
            s[base + 3 * q] = make_float2(t1x - t3y, t1y + t3x);
        }
        __syncthreads();
    }
}

// ---------------- kernel 1: combined kernel spectra A,B per channel pair ----------------
__global__ void __launch_bounds__(TFFT, 1) kf_kernel(const float* __restrict__ K) {
    extern __shared__ float2 s[];
    int tid  = threadIdx.x;
    int pair = blockIdx.x;
    const float* k1 = K + (size_t)(2 * pair) * Ll;
    const float* k2 = K + (size_t)(2 * pair + 1) * Ll;
    for (int n = tid; n < Ll; n += TFFT) s[n] = make_float2(k1[n], k2[n]);
    for (int n = Ll + tid; n < NFFT; n += TFFT) s[n] = make_float2(0.f, 0.f);
    __syncthreads();
    dif_fft(s, tid);
    const float inv = 1.0f / (4.0f * (float)NFFT);
    float4* AB = g_AB + (size_t)pair * (HALF + 1);
    for (int k = tid; k <= HALF; k += TFFT) {
        int pk  = rev4_14(k);
        int kn  = (NFFT - k) & (NFFT - 1);
        int pk2 = rev4_14(kn);
        float2 Z  = s[pk];
        float2 Zp = s[pk2];
        float ax = (Z.x + Z.y + Zp.x + Zp.y) * inv;
        float ay = (Z.y - Z.x + Zp.x - Zp.y) * inv;
        float bx = (Z.x - Z.y + Zp.x - Zp.y) * inv;
        float by = (Z.x + Z.y - Zp.x - Zp.y) * inv;
        AB[k] = make_float4(ax, ay, bx, by);
    }
}

// ---------------- kernel 2: FFT conv + skip per (batch, channel pair) ----------------
__global__ void __launch_bounds__(TFFT, 1) conv_kernel(const float* __restrict__ u,
                                                       const float* __restrict__ D) {
    extern __shared__ float2 s[];
    int tid  = threadIdx.x;
    int pair = blockIdx.x & (NPAIR - 1);
    int b    = blockIdx.x >> 8;
    int h1   = 2 * pair, h2 = h1 + 1;
    const float* u1 = u + ((size_t)b * Hh + h1) * Ll;
    const float* u2 = u + ((size_t)b * Hh + h2) * Ll;
    for (int n = tid; n < Ll; n += TFFT) s[n] = make_float2(u1[n], u2[n]);
    for (int n = Ll + tid; n < NFFT; n += TFFT) s[n] = make_float2(0.f, 0.f);
    __syncthreads();
    dif_fft(s, tid);

    const float4* AB = g_AB + (size_t)pair * (HALF + 1);
    for (int k = tid; k <= HALF; k += TFFT) {
        int pk  = rev4_14(k);
        int kn  = (NFFT - k) & (NFFT - 1);
        int pk2 = rev4_14(kn);
        float2 Z  = s[pk];
        float2 Zp = s[pk2];
        float4 ab = AB[k];
        float vx = Z.x * ab.x - Z.y * ab.y + Zp.x * ab.z + Zp.y * ab.w;
        float vy = Z.x * ab.y + Z.y * ab.x - Zp.y * ab.z + Zp.x * ab.w;
        s[pk] = make_float2(vx, -vy);
        if (k != 0 && k != HALF) {
            float wx =  Zp.x * ab.x + Zp.y * ab.y + Z.x * ab.z - Z.y * ab.w;
            float wy = -Zp.x * ab.y + Zp.y * ab.x - Z.x * ab.w - Z.y * ab.z;
            s[pk2] = make_float2(wx, -wy);
        }
    }
    __syncthreads();
    dit_fft(s, tid);

    float d1 = D[h1], d2 = D[h2];
    float* y1 = g_ymid + ((size_t)b * Hh + h1) * Ll;
    float* y2 = g_ymid + ((size_t)b * Hh + h2) * Ll;
    for (int n = tid; n < Ll; n += TFFT) {
        float2 w = s[n];
        y1[n] = tf32r( w.x + d1 * u1[n]);   // tf32-rna so GEMM mma truncation is exact
        y2[n] = tf32r(-w.y + d2 * u2[n]);
    }
}

// ---------------- kernel 2.5: pre-round W to tf32 (round-to-nearest) ----------------
__global__ void wround_kernel(const float* __restrict__ W) {
    int i = blockIdx.x * 256 + threadIdx.x;
    g_Wr[i] = tf32r(W[i]);
}

// ================= kernel 3: tf32 mma.sync mix GEMM + tanh =================
// out[b,p,l] = tanh( sum_h W[p,h] * Y[b,h,l] ).
// CTA tile: 128 p x 128 l, BK=32, 8 warps (2 x 4), warp tile 64 x 32.
// A = g_Wr rows (row-major, k contiguous) -> As[128][36]  (pad 4: conflict-free frags)
// B = g_ymid rows (l contiguous)          -> Bs[32][136]  (pad 8: conflict-free frags)

#define MIXT 256
#define AS_STR 36
#define BS_STR 136
#define A_BYTES (128 * AS_STR * 4)            /* 18432 */
#define B_BYTES (32 * BS_STR * 4)             /* 17408 */
#define STAGE_BYTES (A_BYTES + B_BYTES)       /* 35840 */
#define MIX_SMEM (2 * STAGE_BYTES)            /* 71680 */

__device__ __forceinline__ uint32_t smem_u32(const void* p) {
    uint32_t a;
    asm("{ .reg .u64 t; cvta.to.shared.u64 t, %1; cvt.u32.u64 %0, t; }" : "=r"(a) : "l"(p));
    return a;
}

__device__ __forceinline__ void mma_tf32(float* c, const uint32_t* a, const uint32_t* b) {
    asm volatile(
        "mma.sync.aligned.m16n8k8.row.col.f32.tf32.tf32.f32 "
        "{%0,%1,%2,%3}, {%4,%5,%6,%7}, {%8,%9}, {%0,%1,%2,%3};"
        : "+f"(c[0]), "+f"(c[1]), "+f"(c[2]), "+f"(c[3])
        : "r"(a[0]), "r"(a[1]), "r"(a[2]), "r"(a[3]), "r"(b[0]), "r"(b[1]));
}

__device__ __forceinline__ void load_stage(const float* __restrict__ Wp,
                                           const float* __restrict__ Yp,
                                           uint32_t smem_stage, int c, int tid) {
    int k0 = c * 32;
    // A: 128 rows x 32 floats; 1024 x 16B; 4 per thread
#pragma unroll
    for (int i = 0; i < 4; ++i) {
        int idx = tid + i * MIXT;
        int row = idx >> 3, seg = idx & 7;
        const float* src = Wp + (size_t)row * Hh + k0 + seg * 4;
        uint32_t dst = smem_stage + (uint32_t)(row * AS_STR + seg * 4) * 4;
        asm volatile("cp.async.cg.shared.global [%0], [%1], 16;" :: "r"(dst), "l"(src));
    }
    // B: 32 rows x 128 floats; 1024 x 16B; 4 per thread
#pragma unroll
    for (int i = 0; i < 4; ++i) {
        int idx = tid + i * MIXT;
        int row = idx >> 5, seg = idx & 31;
        const float* src = Yp + (size_t)(k0 + row) * Ll + seg * 4;
        uint32_t dst = smem_stage + A_BYTES + (uint32_t)(row * BS_STR + seg * 4) * 4;
        asm volatile("cp.async.cg.shared.global [%0], [%1], 16;" :: "r"(dst), "l"(src));
    }
    asm volatile("cp.async.commit_group;" ::: "memory");
}

__global__ void __launch_bounds__(MIXT, 2) mix_tc_kernel(float* __restrict__ out) {
    extern __shared__ char smx[];
    uint32_t sb = smem_u32(smx);
    int tid  = threadIdx.x;
    int lane = tid & 31, wid = tid >> 5;
    int warpM = wid >> 2, warpN = wid & 3;       // 2 x 4
    int g = lane >> 2, tg = lane & 3;

    int b     = blockIdx.z;
    int pTile = blockIdx.y * 128;
    int lTile = blockIdx.x * 128;
    const float* Wp = g_Wr + (size_t)pTile * Hh;
    const float* Yp = g_ymid + (size_t)b * Hh * Ll + lTile;
    float* Ob = out + (size_t)b * Hh * Ll;

    float acc[4][4][4];
#pragma unroll
    for (int mt = 0; mt < 4; ++mt)
#pragma unroll
        for (int nt = 0; nt < 4; ++nt)
#pragma unroll
            for (int r = 0; r < 4; ++r) acc[mt][nt][r] = 0.f;

    load_stage(Wp, Yp, sb, 0, tid);

#pragma unroll 1
    for (int c = 0; c < Hh / 32; ++c) {
        if (c + 1 < Hh / 32) {
            load_stage(Wp, Yp, sb + ((c + 1) & 1) * STAGE_BYTES, c + 1, tid);
            asm volatile("cp.async.wait_group 1;" ::: "memory");
        } else {
            asm volatile("cp.async.wait_group 0;" ::: "memory");
        }
        __syncthreads();

        const float* As = (const float*)(smx + (c & 1) * STAGE_BYTES);
        const float* Bs = (const float*)(smx + (c & 1) * STAGE_BYTES + A_BYTES);
#pragma unroll
        for (int ks = 0; ks < 4; ++ks) {
            uint32_t af[4][4], bf[4][2];
            int kc = ks * 8 + tg;
#pragma unroll
            for (int mt = 0; mt < 4; ++mt) {
                int r0 = warpM * 64 + mt * 16 + g;
                af[mt][0] = __float_as_uint(As[r0 * AS_STR + kc]);
                af[mt][1] = __float_as_uint(As[(r0 + 8) * AS_STR + kc]);
                af[mt][2] = __float_as_uint(As[r0 * AS_STR + kc + 4]);
                af[mt][3] = __float_as_uint(As[(r0 + 8) * AS_STR + kc + 4]);
            }
#pragma unroll
            for (int nt = 0; nt < 4; ++nt) {
                int l = warpN * 32 + nt * 8 + g;
                bf[nt][0] = __float_as_uint(Bs[kc * BS_STR + l]);
                bf[nt][1] = __float_as_uint(Bs[(kc + 4) * BS_STR + l]);
            }
#pragma unroll
            for (int mt = 0; mt < 4; ++mt)
#pragma unroll
                for (int nt = 0; nt < 4; ++nt)
                    mma_tf32(acc[mt][nt], af[mt], bf[nt]);
        }
        __syncthreads();
    }

    // epilogue: tanh + store (two float2 per mma tile)
#pragma unroll
    for (int mt = 0; mt < 4; ++mt) {
        int p0 = pTile + warpM * 64 + mt * 16 + g;
#pragma unroll
        for (int nt = 0; nt < 4; ++nt) {
            int l = lTile + warpN * 32 + nt * 8 + 2 * tg;
            float2 v0 = make_float2(tanhf(acc[mt][nt][0]), tanhf(acc[mt][nt][1]));
            float2 v1 = make_float2(tanhf(acc[mt][nt][2]), tanhf(acc[mt][nt][3]));
            *(float2*)(Ob + (size_t)p0 * Ll + l)       = v0;
            *(float2*)(Ob + (size_t)(p0 + 8) * Ll + l) = v1;
        }
    }
}

// ---------------- launch ----------------
extern "C" void kernel_launch(void* const* d_in, const int* in_sizes, int n_in,
                              void* d_out, int out_size) {
    const float* u = (const float*)d_in[0];
    const float* K = (const float*)d_in[1];
    const float* D = (const float*)d_in[2];
    const float* W = (const float*)d_in[3];
    float* out = (float*)d_out;

    const int smem = NFFT * (int)sizeof(float2);  // 128 KB
    cudaFuncSetAttribute(kf_kernel,   cudaFuncAttributeMaxDynamicSharedMemorySize, smem);
    cudaFuncSetAttribute(conv_kernel, cudaFuncAttributeMaxDynamicSharedMemorySize, smem);
    cudaFuncSetAttribute(mix_tc_kernel, cudaFuncAttributeMaxDynamicSharedMemorySize, MIX_SMEM);

    wround_kernel<<<(Hh * Hh) / 256, 256>>>(W);
    kf_kernel<<<NPAIR, TFFT, smem>>>(K);
    conv_kernel<<<Bb * NPAIR, TFFT, smem>>>(u, D);
    dim3 g(Ll / 128, Hh / 128, Bb);
    mix_tc_kernel<<<g, MIXT, MIX_SMEM>>>(out);
}

// round 8
// speedup vs baseline: 1.8142x; 1.2221x over previous
#include <cuda_runtime.h>
#include <cstdint>

#define Bb    8
#define Hh    512
#define Ll    8192
#define NFFT  16384
#define HALF  8192
#define QTOP  4096   /* NFFT/4 */
#define NPAIR 256    /* H/2 */
#define TFFT  1024
#define NTW   5461   /* 1+4+16+...+4096 */

// ---------------- scratch (device globals; no allocation allowed) ----------------
__device__ float4 g_AB[(size_t)NPAIR * (HALF + 1)];   // per-pair combined spectra A,B
__device__ float  g_ymid[(size_t)Bb * Hh * Ll];       // conv+skip result (B,H,L), tf32-rounded
__device__ float  g_Wr[(size_t)Hh * Hh];              // W pre-rounded to tf32 (rna)
__device__ float2 g_tw1[NTW];                         // twiddle LUT: w, w^2, w^3 per (stage,j)
__device__ float2 g_tw2[NTW];
__device__ float2 g_tw3[NTW];

// ---------------- helpers ----------------
__device__ __forceinline__ float2 cmulf(float2 a, float2 b) {
    return make_float2(a.x * b.x - a.y * b.y, a.x * b.y + a.y * b.x);
}
__device__ __forceinline__ int rev4_14(int k) {
    unsigned r = __brev((unsigned)k) >> 18;
    return (int)(((r & 0x2AAAu) >> 1) | ((r & 0x1555u) << 1));
}
__device__ __forceinline__ float tf32r(float v) {
    uint32_t r;
    asm("cvt.rna.tf32.f32 %0, %1;" : "=r"(r) : "f"(v));
    return __uint_as_float(r);
}

// ---------------- twiddle LUT init ----------------
__global__ void tw_init() {
    int idx = blockIdx.x * 256 + threadIdx.x;
    if (idx >= NTW) return;
    int q = 1, off = 0;
    while (idx >= off + q) { off += q; q <<= 2; }
    int j = idx - off;
    int m = q << 2;
    float ang = -6.283185307179586f * ((float)j / (float)m);
    float s1, c1, s2, c2, s3, c3;
    sincosf(ang, &s1, &c1);
    sincosf(2.0f * ang, &s2, &c2);
    sincosf(3.0f * ang, &s3, &c3);
    g_tw1[idx] = make_float2(c1, s1);
    g_tw2[idx] = make_float2(c2, s2);
    g_tw3[idx] = make_float2(c3, s3);
}

// ---------------- fused load + first DIF stage (m=NFFT, top half of input zero) ----------------
// inputs f1,f2 length L (8192); conceptual x[n] = (f1[n], f2[n]) zero-padded to 16384.
__device__ void dif_first_fused(float2* s, const float* __restrict__ f1,
                                const float* __restrict__ f2, int tid) {
#pragma unroll 2
    for (int i = tid; i < QTOP; i += TFFT) {
        float2 a0 = make_float2(f1[i], f2[i]);
        float2 a1 = make_float2(f1[i + QTOP], f2[i + QTOP]);
        float2 b0 = make_float2(a0.x + a1.x, a0.y + a1.y);
        float2 b1 = make_float2(a0.x + a1.y, a0.y - a1.x);   // a0 - i*a1
        float2 b2 = make_float2(a0.x - a1.x, a0.y - a1.y);
        float2 b3 = make_float2(a0.x - a1.y, a0.y + a1.x);   // a0 + i*a1
        float2 w1 = __ldg(&g_tw1[1365 + i]);
        float2 w2 = __ldg(&g_tw2[1365 + i]);
        float2 w3 = __ldg(&g_tw3[1365 + i]);
        s[i]            = b0;
        s[i + QTOP]     = cmulf(b1, w1);
        s[i + 2 * QTOP] = cmulf(b2, w2);
        s[i + 3 * QTOP] = cmulf(b3, w3);
    }
    __syncthreads();
}

// ---------------- remaining DIF stages: m = 4096 .. 4 ----------------
__device__ void dif_rest(float2* s, int tid) {
#pragma unroll 1
    for (int m = 4096; m >= 4; m >>= 2) {
        int q = m >> 2;
        int off = (q - 1) / 3;
#pragma unroll 2
        for (int i = tid; i < QTOP; i += TFFT) {
            int j = i & (q - 1);
            int base = ((i - j) << 2) + j;
            float2 a0 = s[base], a1 = s[base + q], a2 = s[base + 2 * q], a3 = s[base + 3 * q];
            float t0x = a0.x + a2.x, t0y = a0.y + a2.y;
            float t1x = a0.x - a2.x, t1y = a0.y - a2.y;
            float t2x = a1.x + a3.x, t2y = a1.y + a3.y;
            float t3x = a1.x - a3.x, t3y = a1.y - a3.y;
            float2 b0 = make_float2(t0x + t2x, t0y + t2y);
            float2 b1 = make_float2(t1x + t3y, t1y - t3x);
            float2 b2 = make_float2(t0x - t2x, t0y - t2y);
            float2 b3 = make_float2(t1x - t3y, t1y + t3x);
            float2 w1 = __ldg(&g_tw1[off + j]);
            float2 w2 = __ldg(&g_tw2[off + j]);
            float2 w3 = __ldg(&g_tw3[off + j]);
            s[base]         = b0;
            s[base + q]     = cmulf(b1, w1);
            s[base + 2 * q] = cmulf(b2, w2);
            s[base + 3 * q] = cmulf(b3, w3);
        }
        __syncthreads();
    }
}

// ---------------- DIT stages m = 4 .. 4096 (last stage m=NFFT fused by caller) ----------------
__device__ void dit_rest(float2* s, int tid) {
#pragma unroll 1
    for (int m = 4; m <= 4096; m <<= 2) {
        int q = m >> 2;
        int off = (q - 1) / 3;
#pragma unroll 2
        for (int i = tid; i < QTOP; i += TFFT) {
            int j = i & (q - 1);
            int base = ((i - j) << 2) + j;
            float2 c0 = s[base], c1 = s[base + q], c2 = s[base + 2 * q], c3 = s[base + 3 * q];
            float2 w1 = __ldg(&g_tw1[off + j]);
            float2 w2 = __ldg(&g_tw2[off + j]);
            float2 w3 = __ldg(&g_tw3[off + j]);
            c1 = cmulf(c1, w1);
            c2 = cmulf(c2, w2);
            c3 = cmulf(c3, w3);
            float t0x = c0.x + c2.x, t0y = c0.y + c2.y;
            float t1x = c0.x - c2.x, t1y = c0.y - c2.y;
            float t2x = c1.x + c3.x, t2y = c1.y + c3.y;
            float t3x = c1.x - c3.x, t3y = c1.y - c3.y;
            s[base]         = make_float2(t0x + t2x, t0y + t2y);
            s[base + q]     = make_float2(t1x + t3y, t1y - t3x);
            s[base + 2 * q] = make_float2(t0x - t2x, t0y - t2y);
            s[base + 3 * q] = make_float2(t1x - t3y, t1y + t3x);
        }
        __syncthreads();
    }
}

// ---------------- kernel 1: combined kernel spectra A,B per channel pair ----------------
__global__ void __launch_bounds__(TFFT, 1) kf_kernel(const float* __restrict__ K) {
    extern __shared__ float2 s[];
    int tid  = threadIdx.x;
    int pair = blockIdx.x;
    const float* k1 = K + (size_t)(2 * pair) * Ll;
    const float* k2 = K + (size_t)(2 * pair + 1) * Ll;
    dif_first_fused(s, k1, k2, tid);
    dif_rest(s, tid);
    const float inv = 1.0f / (4.0f * (float)NFFT);
    float4* AB = g_AB + (size_t)pair * (HALF + 1);
    for (int k = tid; k <= HALF; k += TFFT) {
        int pk  = rev4_14(k);
        int kn  = (NFFT - k) & (NFFT - 1);
        int pk2 = rev4_14(kn);
        float2 Z  = s[pk];
        float2 Zp = s[pk2];
        float ax = (Z.x + Z.y + Zp.x + Zp.y) * inv;
        float ay = (Z.y - Z.x + Zp.x - Zp.y) * inv;
        float bx = (Z.x - Z.y + Zp.x - Zp.y) * inv;
        float by = (Z.x + Z.y - Zp.x - Zp.y) * inv;
        AB[k] = make_float4(ax, ay, bx, by);
    }
}

// ---------------- kernel 2: FFT conv + skip per (batch, channel pair) ----------------
__global__ void __launch_bounds__(TFFT, 1) conv_kernel(const float* __restrict__ u,
                                                       const float* __restrict__ D) {
    extern __shared__ float2 s[];
    int tid  = threadIdx.x;
    int pair = blockIdx.x & (NPAIR - 1);
    int b    = blockIdx.x >> 8;
    int h1   = 2 * pair, h2 = h1 + 1;
    const float* u1 = u + ((size_t)b * Hh + h1) * Ll;
    const float* u2 = u + ((size_t)b * Hh + h2) * Ll;
    dif_first_fused(s, u1, u2, tid);
    dif_rest(s, tid);

    const float4* AB = g_AB + (size_t)pair * (HALF + 1);
    for (int k = tid; k <= HALF; k += TFFT) {
        int pk  = rev4_14(k);
        int kn  = (NFFT - k) & (NFFT - 1);
        int pk2 = rev4_14(kn);
        float2 Z  = s[pk];
        float2 Zp = s[pk2];
        float4 ab = AB[k];
        float vx = Z.x * ab.x - Z.y * ab.y + Zp.x * ab.z + Zp.y * ab.w;
        float vy = Z.x * ab.y + Z.y * ab.x - Zp.y * ab.z + Zp.x * ab.w;
        s[pk] = make_float2(vx, -vy);
        if (k != 0 && k != HALF) {
            float wx =  Zp.x * ab.x + Zp.y * ab.y + Z.x * ab.z - Z.y * ab.w;
            float wy = -Zp.x * ab.y + Zp.y * ab.x - Z.x * ab.w - Z.y * ab.z;
            s[pk2] = make_float2(wx, -wy);
        }
    }
    __syncthreads();
    dit_rest(s, tid);

    // fused last DIT stage (m=NFFT): only outputs n<8192 are kept; write y directly.
    float d1 = D[h1], d2 = D[h2];
    float* y1 = g_ymid + ((size_t)b * Hh + h1) * Ll;
    float* y2 = g_ymid + ((size_t)b * Hh + h2) * Ll;
#pragma unroll 2
    for (int i = tid; i < QTOP; i += TFFT) {
        float2 c0 = s[i], c1 = s[i + QTOP], c2 = s[i + 2 * QTOP], c3 = s[i + 3 * QTOP];
        float2 w1 = __ldg(&g_tw1[1365 + i]);
        float2 w2 = __ldg(&g_tw2[1365 + i]);
        float2 w3 = __ldg(&g_tw3[1365 + i]);
        c1 = cmulf(c1, w1);
        c2 = cmulf(c2, w2);
        c3 = cmulf(c3, w3);
        float t0x = c0.x + c2.x, t0y = c0.y + c2.y;
        float t1x = c0.x - c2.x, t1y = c0.y - c2.y;
        float t2x = c1.x + c3.x, t2y = c1.y + c3.y;
        float t3x = c1.x - c3.x, t3y = c1.y - c3.y;
        // out[i] = t0 + t2 ; out[i+4096] = t1 - i*t3 (outputs >= 8192 discarded)
        float o0x = t0x + t2x, o0y = t0y + t2y;
        float o1x = t1x + t3y, o1y = t1y - t3x;
        y1[i]        = tf32r( o0x + d1 * u1[i]);
        y2[i]        = tf32r(-o0y + d2 * u2[i]);
        y1[i + QTOP] = tf32r( o1x + d1 * u1[i + QTOP]);
        y2[i + QTOP] = tf32r(-o1y + d2 * u2[i + QTOP]);
    }
}

// ---------------- kernel 2.5: pre-round W to tf32 (round-to-nearest) ----------------
__global__ void wround_kernel(const float* __restrict__ W) {
    int i = blockIdx.x * 256 + threadIdx.x;
    g_Wr[i] = tf32r(W[i]);
}

// ================= kernel 3: tf32 mma.sync mix GEMM + tanh =================
#define MIXT 256
#define AS_STR 36
#define BS_STR 136
#define A_BYTES (128 * AS_STR * 4)
#define B_BYTES (32 * BS_STR * 4)
#define STAGE_BYTES (A_BYTES + B_BYTES)
#define MIX_SMEM (2 * STAGE_BYTES)

__device__ __forceinline__ uint32_t smem_u32(const void* p) {
    uint32_t a;
    asm("{ .reg .u64 t; cvta.to.shared.u64 t, %1; cvt.u32.u64 %0, t; }" : "=r"(a) : "l"(p));
    return a;
}
__device__ __forceinline__ void mma_tf32(float* c, const uint32_t* a, const uint32_t* b) {
    asm volatile(
        "mma.sync.aligned.m16n8k8.row.col.f32.tf32.tf32.f32 "
        "{%0,%1,%2,%3}, {%4,%5,%6,%7}, {%8,%9}, {%0,%1,%2,%3};"
        : "+f"(c[0]), "+f"(c[1]), "+f"(c[2]), "+f"(c[3])
        : "r"(a[0]), "r"(a[1]), "r"(a[2]), "r"(a[3]), "r"(b[0]), "r"(b[1]));
}
__device__ __forceinline__ void load_stage(const float* __restrict__ Wp,
                                           const float* __restrict__ Yp,
                                           uint32_t smem_stage, int c, int tid) {
    int k0 = c * 32;
#pragma unroll
    for (int i = 0; i < 4; ++i) {
        int idx = tid + i * MIXT;
        int row = idx >> 3, seg = idx & 7;
        const float* src = Wp + (size_t)row * Hh + k0 + seg * 4;
        uint32_t dst = smem_stage + (uint32_t)(row * AS_STR + seg * 4) * 4;
        asm volatile("cp.async.cg.shared.global [%0], [%1], 16;" :: "r"(dst), "l"(src));
    }
#pragma unroll
    for (int i = 0; i < 4; ++i) {
        int idx = tid + i * MIXT;
        int row = idx >> 5, seg = idx & 31;
        const float* src = Yp + (size_t)(k0 + row) * Ll + seg * 4;
        uint32_t dst = smem_stage + A_BYTES + (uint32_t)(row * BS_STR + seg * 4) * 4;
        asm volatile("cp.async.cg.shared.global [%0], [%1], 16;" :: "r"(dst), "l"(src));
    }
    asm volatile("cp.async.commit_group;" ::: "memory");
}

__global__ void __launch_bounds__(MIXT, 2) mix_tc_kernel(float* __restrict__ out) {
    extern __shared__ char smx[];
    uint32_t sb = smem_u32(smx);
    int tid  = threadIdx.x;
    int lane = tid & 31, wid = tid >> 5;
    int warpM = wid >> 2, warpN = wid & 3;
    int g = lane >> 2, tg = lane & 3;

    int b     = blockIdx.z;
    int pTile = blockIdx.y * 128;
    int lTile = blockIdx.x * 128;
    const float* Wp = g_Wr + (size_t)pTile * Hh;
    const float* Yp = g_ymid + (size_t)b * Hh * Ll + lTile;
    float* Ob = out + (size_t)b * Hh * Ll;

    float acc[4][4][4];
#pragma unroll
    for (int mt = 0; mt < 4; ++mt)
#pragma unroll
        for (int nt = 0; nt < 4; ++nt)
#pragma unroll
            for (int r = 0; r < 4; ++r) acc[mt][nt][r] = 0.f;

    load_stage(Wp, Yp, sb, 0, tid);

#pragma unroll 1
    for (int c = 0; c < Hh / 32; ++c) {
        if (c + 1 < Hh / 32) {
            load_stage(Wp, Yp, sb + ((c + 1) & 1) * STAGE_BYTES, c + 1, tid);
            asm volatile("cp.async.wait_group 1;" ::: "memory");
        } else {
            asm volatile("cp.async.wait_group 0;" ::: "memory");
        }
        __syncthreads();

        const float* As = (const float*)(smx + (c & 1) * STAGE_BYTES);
        const float* Bs = (const float*)(smx + (c & 1) * STAGE_BYTES + A_BYTES);
#pragma unroll
        for (int ks = 0; ks < 4; ++ks) {
            uint32_t af[4][4], bf[4][2];
            int kc = ks * 8 + tg;
#pragma unroll
            for (int mt = 0; mt < 4; ++mt) {
                int r0 = warpM * 64 + mt * 16 + g;
                af[mt][0] = __float_as_uint(As[r0 * AS_STR + kc]);
                af[mt][1] = __float_as_uint(As[(r0 + 8) * AS_STR + kc]);
                af[mt][2] = __float_as_uint(As[r0 * AS_STR + kc + 4]);
                af[mt][3] = __float_as_uint(As[(r0 + 8) * AS_STR + kc + 4]);
            }
#pragma unroll
            for (int nt = 0; nt < 4; ++nt) {
                int l = warpN * 32 + nt * 8 + g;
                bf[nt][0] = __float_as_uint(Bs[kc * BS_STR + l]);
                bf[nt][1] = __float_as_uint(Bs[(kc + 4) * BS_STR + l]);
            }
#pragma unroll
            for (int mt = 0; mt < 4; ++mt)
#pragma unroll
                for (int nt = 0; nt < 4; ++nt)
                    mma_tf32(acc[mt][nt], af[mt], bf[nt]);
        }
        __syncthreads();
    }

#pragma unroll
    for (int mt = 0; mt < 4; ++mt) {
        int p0 = pTile + warpM * 64 + mt * 16 + g;
#pragma unroll
        for (int nt = 0; nt < 4; ++nt) {
            int l = lTile + warpN * 32 + nt * 8 + 2 * tg;
            float2 v0 = make_float2(tanhf(acc[mt][nt][0]), tanhf(acc[mt][nt][1]));
            float2 v1 = make_float2(tanhf(acc[mt][nt][2]), tanhf(acc[mt][nt][3]));
            *(float2*)(Ob + (size_t)p0 * Ll + l)       = v0;
            *(float2*)(Ob + (size_t)(p0 + 8) * Ll + l) = v1;
        }
    }
}

// ---------------- launch ----------------
extern "C" void kernel_launch(void* const* d_in, const int* in_sizes, int n_in,
                              void* d_out, int out_size) {
    const float* u = (const float*)d_in[0];
    const float* K = (const float*)d_in[1];
    const float* D = (const float*)d_in[2];
    const float* W = (const float*)d_in[3];
    float* out = (float*)d_out;

    const int smem = NFFT * (int)sizeof(float2);  // 128 KB
    cudaFuncSetAttribute(kf_kernel,   cudaFuncAttributeMaxDynamicSharedMemorySize, smem);
    cudaFuncSetAttribute(conv_kernel, cudaFuncAttributeMaxDynamicSharedMemorySize, smem);
    cudaFuncSetAttribute(mix_tc_kernel, cudaFuncAttributeMaxDynamicSharedMemorySize, MIX_SMEM);

    tw_init<<<(NTW + 255) / 256, 256>>>();
    wround_kernel<<<(Hh * Hh) / 256, 256>>>(W);
    kf_kernel<<<NPAIR, TFFT, smem>>>(K);
    conv_kernel<<<Bb * NPAIR, TFFT, smem>>>(u, D);
    dim3 g(Ll / 128, Hh / 128, Bb);
    mix_tc_kernel<<<g, MIXT, MIX_SMEM>>>(out);
}